// round 2
// baseline (speedup 1.0000x reference)
#include <cuda_runtime.h>
#include <cuda_bf16.h>
#include <cstdint>

#define NROWS 8192
#define BHALF 4096
#define DDIM  512
#define INV_T 14.285714285714286f
// log2(e)/T
#define EXP_SCALE 20.60992915555662f
#define PARTS 128              // 8192/64: one partial per 64-col span
#define SROW 40                // padded smem row (bf16 units), bank-conflict-free frags

// ---------------- device scratch (no allocation allowed) ----------------
__device__ __nv_bfloat16 g_fb16[(size_t)NROWS * DDIM];      // 8 MB normalized bf16
__device__ float         g_f32 [(size_t)NROWS * DDIM];      // 16 MB normalized fp32
__device__ float         g_partial[(size_t)PARTS * NROWS];  // 4 MB per-span exp sums
__device__ float         g_pos [NROWS];
__device__ float         g_loss[NROWS];

// ---------------- PTX helpers (plain sm_103-legal only) ----------------
__device__ __forceinline__ uint32_t smem_u32(const void* p) {
    uint32_t a;
    asm("{ .reg .u64 t; cvta.to.shared.u64 t, %1; cvt.u32.u64 %0, t; }" : "=r"(a) : "l"(p));
    return a;
}

__device__ __forceinline__ void cp16(void* s, const void* g) {
    uint32_t sa = smem_u32(s);
    asm volatile("cp.async.cg.shared.global [%0], [%1], 16;" :: "r"(sa), "l"(g) : "memory");
}
__device__ __forceinline__ void cp_commit() {
    asm volatile("cp.async.commit_group;" ::: "memory");
}
template<int N> __device__ __forceinline__ void cp_wait() {
    asm volatile("cp.async.wait_group %0;" :: "n"(N) : "memory");
}

__device__ __forceinline__ void mma16816(float* c, const uint32_t* a, uint32_t b0, uint32_t b1) {
    asm volatile(
        "mma.sync.aligned.m16n8k16.row.col.f32.bf16.bf16.f32 "
        "{%0,%1,%2,%3}, {%4,%5,%6,%7}, {%8,%9}, {%0,%1,%2,%3};"
        : "+f"(c[0]), "+f"(c[1]), "+f"(c[2]), "+f"(c[3])
        : "r"(a[0]), "r"(a[1]), "r"(a[2]), "r"(a[3]), "r"(b0), "r"(b1));
}

__device__ __forceinline__ float ex2f(float x) {
    float y;
    asm("ex2.approx.ftz.f32 %0, %1;" : "=f"(y) : "f"(x));
    return y;
}

// ---------------- kernel 1: L2-normalize rows, emit fp32 + bf16 ----------------
__global__ void norm_kernel(const float* __restrict__ logits, const float* __restrict__ label) {
    int row = blockIdx.x;
    int t = threadIdx.x;                  // 128 threads, 1 float4 each
    const float* src = (row < BHALF) ? (logits + (size_t)row * DDIM)
                                     : (label + (size_t)(row - BHALF) * DDIM);
    float4 v = ((const float4*)src)[t];
    float ss = v.x * v.x + v.y * v.y + v.z * v.z + v.w * v.w;
    #pragma unroll
    for (int o = 16; o; o >>= 1) ss += __shfl_xor_sync(0xffffffffu, ss, o);
    __shared__ float ws[4];
    if ((t & 31) == 0) ws[t >> 5] = ss;
    __syncthreads();
    float tot = ws[0] + ws[1] + ws[2] + ws[3];
    float scale = 1.0f / fmaxf(sqrtf(tot), 1e-12f);
    float4 o4 = make_float4(v.x * scale, v.y * scale, v.z * scale, v.w * scale);
    ((float4*)(g_f32 + (size_t)row * DDIM))[t] = o4;
    __nv_bfloat162 h0, h1;
    h0.x = __float2bfloat16(o4.x); h0.y = __float2bfloat16(o4.y);
    h1.x = __float2bfloat16(o4.z); h1.y = __float2bfloat16(o4.w);
    uint2 packed;
    packed.x = *reinterpret_cast<uint32_t*>(&h0);
    packed.y = *reinterpret_cast<uint32_t*>(&h1);
    ((uint2*)(g_fb16 + (size_t)row * DDIM))[t] = packed;
}

// ---------------- kernel 2: positives in fp32 (1 warp per row) ----------------
__global__ void pos_kernel() {
    int w = (int)((blockIdx.x * blockDim.x + threadIdx.x) >> 5);
    int lane = threadIdx.x & 31;
    if (w >= NROWS) return;
    const float4* a = (const float4*)(g_f32 + (size_t)w * DDIM);
    const float4* b = (const float4*)(g_f32 + (size_t)((w + BHALF) & (NROWS - 1)) * DDIM);
    float s = 0.f;
    #pragma unroll 4
    for (int i = lane; i < DDIM / 4; i += 32) {
        float4 x = a[i], y = b[i];
        s += x.x * y.x + x.y * y.y + x.z * y.z + x.w * y.w;
    }
    #pragma unroll
    for (int o = 16; o; o >>= 1) s += __shfl_xor_sync(0xffffffffu, s, o);
    if (lane == 0) g_pos[w] = s * INV_T;
}

// ---------------- kernel 3: 128x128 sim tile via mma.sync + exp-sum epilogue ----
// 8 warps: warp_m = w&3 (32 rows each), warp_n = w>>2 (64 cols each).
// K = 512 in 16 chunks of 32, cp.async double-buffered.
__global__ void __launch_bounds__(256) sim_kernel() {
    __shared__ __nv_bfloat16 sA[2][128 * SROW];
    __shared__ __nv_bfloat16 sB[2][128 * SROW];

    int tid = threadIdx.x;
    int w = tid >> 5, lane = tid & 31;
    int g = lane >> 2, t = lane & 3;
    int warp_m = w & 3, warp_n = w >> 2;
    int ct = blockIdx.x, rt = blockIdx.y;

    const __nv_bfloat16* Ag = g_fb16 + (size_t)rt * 128 * DDIM;
    const __nv_bfloat16* Bg = g_fb16 + (size_t)ct * 128 * DDIM;

    float acc[2][8][4];
    #pragma unroll
    for (int mf = 0; mf < 2; mf++)
        #pragma unroll
        for (int nf = 0; nf < 8; nf++)
            #pragma unroll
            for (int j = 0; j < 4; j++) acc[mf][nf][j] = 0.f;

    // issue one 32-wide K chunk into buffer `buf`
    auto issue = [&](int buf, int kc) {
        #pragma unroll
        for (int i = 0; i < 2; i++) {
            int idx = tid + 256 * i;        // 0..511
            int row = idx >> 2, seg = idx & 3;
            const __nv_bfloat16* ga = Ag + (size_t)row * DDIM + kc * 32 + seg * 8;
            const __nv_bfloat16* gb = Bg + (size_t)row * DDIM + kc * 32 + seg * 8;
            cp16(&sA[buf][row * SROW + seg * 8], ga);
            cp16(&sB[buf][row * SROW + seg * 8], gb);
        }
        cp_commit();
    };

    issue(0, 0);

    for (int kc = 0; kc < 16; kc++) {
        if (kc + 1 < 16) {
            issue((kc + 1) & 1, kc + 1);
            cp_wait<1>();
        } else {
            cp_wait<0>();
        }
        __syncthreads();

        const __nv_bfloat16* a_s = sA[kc & 1];
        const __nv_bfloat16* b_s = sB[kc & 1];

        #pragma unroll
        for (int ks = 0; ks < 2; ks++) {
            uint32_t afr[2][4];
            #pragma unroll
            for (int mf = 0; mf < 2; mf++) {
                int r0 = warp_m * 32 + mf * 16 + g;
                const __nv_bfloat16* pa = a_s + ks * 16 + 2 * t;
                afr[mf][0] = *(const uint32_t*)(pa + (size_t)r0 * SROW);
                afr[mf][1] = *(const uint32_t*)(pa + (size_t)(r0 + 8) * SROW);
                afr[mf][2] = *(const uint32_t*)(pa + (size_t)r0 * SROW + 8);
                afr[mf][3] = *(const uint32_t*)(pa + (size_t)(r0 + 8) * SROW + 8);
            }
            #pragma unroll
            for (int nf = 0; nf < 8; nf++) {
                int rb = warp_n * 64 + nf * 8 + g;
                const __nv_bfloat16* pb = b_s + (size_t)rb * SROW + ks * 16 + 2 * t;
                uint32_t b0 = *(const uint32_t*)(pb);
                uint32_t b1 = *(const uint32_t*)(pb + 8);
                mma16816(acc[0][nf], afr[0], b0, b1);
                mma16816(acc[1][nf], afr[1], b0, b1);
            }
        }
        __syncthreads();
    }

    // epilogue: per-row sum of exp(sim/T) over this warp's 64-col span, diag masked
    #pragma unroll
    for (int mf = 0; mf < 2; mf++) {
        int r_lo = rt * 128 + warp_m * 32 + mf * 16 + g;
        int r_hi = r_lo + 8;
        float s0 = 0.f, s1 = 0.f;
        #pragma unroll
        for (int nf = 0; nf < 8; nf++) {
            int c0 = ct * 128 + warp_n * 64 + nf * 8 + 2 * t;
            const float* c = acc[mf][nf];
            float e0 = ex2f(c[0] * EXP_SCALE);
            float e1 = ex2f(c[1] * EXP_SCALE);
            float e2 = ex2f(c[2] * EXP_SCALE);
            float e3 = ex2f(c[3] * EXP_SCALE);
            if (c0     != r_lo) s0 += e0;
            if (c0 + 1 != r_lo) s0 += e1;
            if (c0     != r_hi) s1 += e2;
            if (c0 + 1 != r_hi) s1 += e3;
        }
        s0 += __shfl_xor_sync(0xffffffffu, s0, 1);
        s0 += __shfl_xor_sync(0xffffffffu, s0, 2);
        s1 += __shfl_xor_sync(0xffffffffu, s1, 1);
        s1 += __shfl_xor_sync(0xffffffffu, s1, 2);
        if (t == 0) {
            size_t part = (size_t)(ct * 2 + warp_n) * NROWS;
            g_partial[part + r_lo] = s0;
            g_partial[part + r_hi] = s1;
        }
    }
}

// ---------------- kernel 4: per-row lse - pos ----------------
__global__ void reduce1_kernel() {
    int r = blockIdx.x * 128 + threadIdx.x;
    float s = 0.f;
    #pragma unroll 8
    for (int t = 0; t < PARTS; t++) s += g_partial[(size_t)t * NROWS + r];
    g_loss[r] = logf(s) - g_pos[r];
}

// ---------------- kernel 5: mean ----------------
__global__ void reduce2_kernel(float* __restrict__ out) {
    int t = threadIdx.x;   // 256
    float acc = 0.f;
    for (int r = t; r < NROWS; r += 256) acc += g_loss[r];
    #pragma unroll
    for (int o = 16; o; o >>= 1) acc += __shfl_xor_sync(0xffffffffu, acc, o);
    __shared__ float ws[8];
    if ((t & 31) == 0) ws[t >> 5] = acc;
    __syncthreads();
    if (t == 0) {
        float s = 0.f;
        #pragma unroll
        for (int i = 0; i < 8; i++) s += ws[i];
        out[0] = s * (1.0f / (float)NROWS);
    }
}

// ---------------- launch ----------------
extern "C" void kernel_launch(void* const* d_in, const int* in_sizes, int n_in,
                              void* d_out, int out_size) {
    const float* logits = (const float*)d_in[0];
    const float* label  = (const float*)d_in[1];
    float* out = (float*)d_out;

    norm_kernel<<<NROWS, 128>>>(logits, label);
    pos_kernel<<<NROWS / 8, 256>>>();
    sim_kernel<<<dim3(64, 64), 256>>>();
    reduce1_kernel<<<64, 128>>>();
    reduce2_kernel<<<1, 256>>>(out);
}

// round 4
// speedup vs baseline: 2.0857x; 2.0857x over previous
#include <cuda_runtime.h>
#include <cuda_bf16.h>
#include <cstdint>
#include <cmath>

#define NROWS 8192
#define BHALF 4096
#define DDIM  512
#define INV_T 14.285714285714286f
// log2(e)/T
#define EXP_SCALE 20.60992915555662f
#define SPANS 128              // one partial per 64-col span (collision-free)
#define SROW 40                // padded smem row (bf16 units): 80B, conflict-free
#define NTILES 2080            // 64*65/2 upper-triangle tiles

// ---------------- device scratch (no allocation allowed) ----------------
__device__ __nv_bfloat16 g_fb16[(size_t)NROWS * DDIM];      // 8 MB normalized bf16
__device__ float         g_f32 [(size_t)NROWS * DDIM];      // 16 MB normalized fp32
__device__ float         g_partial[(size_t)NROWS * SPANS];  // 4 MB [row][span]
__device__ float         g_pos [NROWS];
__device__ float         g_loss[NROWS];

// ---------------- PTX helpers (plain sm_103-legal only) ----------------
__device__ __forceinline__ uint32_t smem_u32(const void* p) {
    uint32_t a;
    asm("{ .reg .u64 t; cvta.to.shared.u64 t, %1; cvt.u32.u64 %0, t; }" : "=r"(a) : "l"(p));
    return a;
}

__device__ __forceinline__ void cp16(void* s, const void* g) {
    uint32_t sa = smem_u32(s);
    asm volatile("cp.async.cg.shared.global [%0], [%1], 16;" :: "r"(sa), "l"(g) : "memory");
}
__device__ __forceinline__ void cp_commit() {
    asm volatile("cp.async.commit_group;" ::: "memory");
}
template<int N> __device__ __forceinline__ void cp_wait() {
    asm volatile("cp.async.wait_group %0;" :: "n"(N) : "memory");
}

__device__ __forceinline__ void ldsm_x4(uint32_t* r, uint32_t addr) {
    asm volatile("ldmatrix.sync.aligned.m8n8.x4.shared.b16 {%0,%1,%2,%3}, [%4];"
                 : "=r"(r[0]), "=r"(r[1]), "=r"(r[2]), "=r"(r[3]) : "r"(addr));
}

__device__ __forceinline__ void mma16816(float* c, const uint32_t* a, uint32_t b0, uint32_t b1) {
    asm volatile(
        "mma.sync.aligned.m16n8k16.row.col.f32.bf16.bf16.f32 "
        "{%0,%1,%2,%3}, {%4,%5,%6,%7}, {%8,%9}, {%0,%1,%2,%3};"
        : "+f"(c[0]), "+f"(c[1]), "+f"(c[2]), "+f"(c[3])
        : "r"(a[0]), "r"(a[1]), "r"(a[2]), "r"(a[3]), "r"(b0), "r"(b1));
}

__device__ __forceinline__ float ex2f(float x) {
    float y;
    asm("ex2.approx.ftz.f32 %0, %1;" : "=f"(y) : "f"(x));
    return y;
}

// ---------------- kernel 1: L2-normalize rows, emit fp32 + bf16 ----------------
__global__ void norm_kernel(const float* __restrict__ logits, const float* __restrict__ label) {
    int row = blockIdx.x;
    int t = threadIdx.x;                  // 128 threads, 1 float4 each
    const float* src = (row < BHALF) ? (logits + (size_t)row * DDIM)
                                     : (label + (size_t)(row - BHALF) * DDIM);
    float4 v = ((const float4*)src)[t];
    float ss = v.x * v.x + v.y * v.y + v.z * v.z + v.w * v.w;
    #pragma unroll
    for (int o = 16; o; o >>= 1) ss += __shfl_xor_sync(0xffffffffu, ss, o);
    __shared__ float ws[4];
    if ((t & 31) == 0) ws[t >> 5] = ss;
    __syncthreads();
    float tot = ws[0] + ws[1] + ws[2] + ws[3];
    float scale = 1.0f / fmaxf(sqrtf(tot), 1e-12f);
    float4 o4 = make_float4(v.x * scale, v.y * scale, v.z * scale, v.w * scale);
    ((float4*)(g_f32 + (size_t)row * DDIM))[t] = o4;
    __nv_bfloat162 h0, h1;
    h0.x = __float2bfloat16(o4.x); h0.y = __float2bfloat16(o4.y);
    h1.x = __float2bfloat16(o4.z); h1.y = __float2bfloat16(o4.w);
    uint2 packed;
    packed.x = *reinterpret_cast<uint32_t*>(&h0);
    packed.y = *reinterpret_cast<uint32_t*>(&h1);
    ((uint2*)(g_fb16 + (size_t)row * DDIM))[t] = packed;
}

// ---------------- kernel 2: positives in fp32 (1 warp per row) ----------------
__global__ void pos_kernel() {
    int w = (int)((blockIdx.x * blockDim.x + threadIdx.x) >> 5);
    int lane = threadIdx.x & 31;
    if (w >= NROWS) return;
    const float4* a = (const float4*)(g_f32 + (size_t)w * DDIM);
    const float4* b = (const float4*)(g_f32 + (size_t)((w + BHALF) & (NROWS - 1)) * DDIM);
    float s = 0.f;
    #pragma unroll 4
    for (int i = lane; i < DDIM / 4; i += 32) {
        float4 x = a[i], y = b[i];
        s += x.x * y.x + x.y * y.y + x.z * y.z + x.w * y.w;
    }
    #pragma unroll
    for (int o = 16; o; o >>= 1) s += __shfl_xor_sync(0xffffffffu, s, o);
    if (lane == 0) g_pos[w] = s * INV_T;
}

// ---------------- kernel 3: symmetric 128x128 sim tiles (upper triangle) -------
// 4 warps, warp tile 64x64 (warp_m = w&1, warp_n = w>>1). K chunks of 32,
// double-buffered cp.async, ldmatrix.x4 frags. Off-diagonal tiles emit both
// row-sums (span ct*2+warp_n) and col-sums (span rt*2+warp_m, transposed tile).
__global__ void __launch_bounds__(128) sim_kernel() {
    __shared__ __nv_bfloat16 sA[2][128 * SROW];
    __shared__ __nv_bfloat16 sB[2][128 * SROW];

    int tid = threadIdx.x;
    int w = tid >> 5, lane = tid & 31;
    int g = lane >> 2, t = lane & 3;
    int warp_m = w & 1, warp_n = w >> 1;

    // decode upper-triangle tile (rt, ct), ct >= rt
    int u = blockIdx.x;
    int rt = (int)((129.0 - sqrt(129.0 * 129.0 - 8.0 * (double)u)) * 0.5);
    while (64 * (rt + 1) - ((rt + 1) * rt) / 2 <= u) rt++;
    while (64 * rt - (rt * (rt - 1)) / 2 > u) rt--;
    int ct = rt + (u - (64 * rt - (rt * (rt - 1)) / 2));
    bool diag = (rt == ct);

    const __nv_bfloat16* Ag = g_fb16 + (size_t)rt * 128 * DDIM;
    const __nv_bfloat16* Bg = g_fb16 + (size_t)ct * 128 * DDIM;

    float acc[4][8][4];
    #pragma unroll
    for (int mf = 0; mf < 4; mf++)
        #pragma unroll
        for (int nf = 0; nf < 8; nf++)
            #pragma unroll
            for (int j = 0; j < 4; j++) acc[mf][nf][j] = 0.f;

    // issue one 32-wide K chunk into buffer `buf` (8 cp16 per thread)
    auto issue = [&](int buf, int kc) {
        #pragma unroll
        for (int i = 0; i < 4; i++) {
            int idx = tid + 128 * i;        // 0..511
            int row = idx >> 2, seg = idx & 3;
            size_t goff = (size_t)row * DDIM + kc * 32 + seg * 8;
            int soff = row * SROW + seg * 8;
            cp16(&sA[buf][soff], Ag + goff);
            cp16(&sB[buf][soff], Bg + goff);
        }
        cp_commit();
    };

    uint32_t sAb = smem_u32(&sA[0][0]);
    uint32_t sBb = smem_u32(&sB[0][0]);
    const uint32_t bufstep = 128 * SROW * 2;   // bytes per buffer

    issue(0, 0);

    for (int kc = 0; kc < 16; kc++) {
        if (kc + 1 < 16) {
            issue((kc + 1) & 1, kc + 1);
            cp_wait<1>();
        } else {
            cp_wait<0>();
        }
        __syncthreads();

        uint32_t aBase = sAb + (kc & 1) * bufstep;
        uint32_t bBase = sBb + (kc & 1) * bufstep;

        #pragma unroll
        for (int ks = 0; ks < 2; ks++) {
            // A frags: 4 x ldmatrix.x4 (mf = 0..3)
            uint32_t afr[4][4];
            {
                int mrow = lane & 7;
                int msel = lane >> 3;                 // 0..3
                int rofs = (msel & 1) * 8 + mrow;
                int cofs = ks * 16 + (msel >> 1) * 8;
                #pragma unroll
                for (int mf = 0; mf < 4; mf++) {
                    int row = warp_m * 64 + mf * 16 + rofs;
                    ldsm_x4(afr[mf], aBase + (uint32_t)(row * SROW + cofs) * 2);
                }
            }
            // B frags: 4 x ldmatrix.x4, each covers 2 nf
            uint32_t bfr[8][2];
            {
                int mrow = lane & 7;
                int msel = lane >> 3;
                int rofs = (msel >> 1) * 8 + mrow;    // second matrix pair = nf+1
                int cofs = ks * 16 + (msel & 1) * 8;
                #pragma unroll
                for (int np = 0; np < 4; np++) {
                    uint32_t r4[4];
                    int row = warp_n * 64 + np * 16 + rofs;
                    ldsm_x4(r4, bBase + (uint32_t)(row * SROW + cofs) * 2);
                    bfr[np * 2][0]     = r4[0];
                    bfr[np * 2][1]     = r4[1];
                    bfr[np * 2 + 1][0] = r4[2];
                    bfr[np * 2 + 1][1] = r4[3];
                }
            }
            #pragma unroll
            for (int mf = 0; mf < 4; mf++)
                #pragma unroll
                for (int nf = 0; nf < 8; nf++)
                    mma16816(acc[mf][nf], afr[mf], bfr[nf][0], bfr[nf][1]);
        }
        __syncthreads();
    }

    // -------- epilogue: exp, diag mask, row sums + (off-diag) col sums --------
    int rbase = rt * 128 + warp_m * 64;
    int cbase = ct * 128 + warp_n * 64;
    float rs[4][2];
    #pragma unroll
    for (int mf = 0; mf < 4; mf++) { rs[mf][0] = 0.f; rs[mf][1] = 0.f; }

    #pragma unroll
    for (int nf = 0; nf < 8; nf++) {
        float cs0 = 0.f, cs1 = 0.f;
        int c0 = cbase + nf * 8 + 2 * t;
        #pragma unroll
        for (int mf = 0; mf < 4; mf++) {
            const float* c = acc[mf][nf];
            float e0 = ex2f(c[0] * EXP_SCALE);
            float e1 = ex2f(c[1] * EXP_SCALE);
            float e2 = ex2f(c[2] * EXP_SCALE);
            float e3 = ex2f(c[3] * EXP_SCALE);
            if (diag) {
                int r0 = rbase + mf * 16 + g;
                if (c0     == r0)     e0 = 0.f;
                if (c0 + 1 == r0)     e1 = 0.f;
                if (c0     == r0 + 8) e2 = 0.f;
                if (c0 + 1 == r0 + 8) e3 = 0.f;
            }
            rs[mf][0] += e0 + e1;
            rs[mf][1] += e2 + e3;
            cs0 += e0 + e2;
            cs1 += e1 + e3;
        }
        if (!diag) {
            // reduce over g (lanes differing in bits 2..4)
            #pragma unroll
            for (int o = 4; o <= 16; o <<= 1) {
                cs0 += __shfl_xor_sync(0xffffffffu, cs0, o);
                cs1 += __shfl_xor_sync(0xffffffffu, cs1, o);
            }
            if (g == 0) {
                int span = rt * 2 + warp_m;   // transposed contribution: col block rt, half warp_m
                g_partial[(size_t)c0 * SPANS + span]       = cs0;
                g_partial[(size_t)(c0 + 1) * SPANS + span] = cs1;
            }
        }
    }
    #pragma unroll
    for (int mf = 0; mf < 4; mf++) {
        float s0 = rs[mf][0], s1 = rs[mf][1];
        s0 += __shfl_xor_sync(0xffffffffu, s0, 1);
        s0 += __shfl_xor_sync(0xffffffffu, s0, 2);
        s1 += __shfl_xor_sync(0xffffffffu, s1, 1);
        s1 += __shfl_xor_sync(0xffffffffu, s1, 2);
        if (t == 0) {
            int r0 = rbase + mf * 16 + g;
            int span = ct * 2 + warp_n;       // row sums: col block ct, half warp_n
            g_partial[(size_t)r0 * SPANS + span]       = s0;
            g_partial[(size_t)(r0 + 8) * SPANS + span] = s1;
        }
    }
}

// ---------------- kernel 4: per-row lse - pos (1 warp per row) ----------------
__global__ void reduce1_kernel() {
    int warp = blockIdx.x * 8 + (threadIdx.x >> 5);
    int lane = threadIdx.x & 31;
    const float* p = g_partial + (size_t)warp * SPANS;
    float s = p[lane] + p[lane + 32] + p[lane + 64] + p[lane + 96];
    #pragma unroll
    for (int o = 16; o; o >>= 1) s += __shfl_xor_sync(0xffffffffu, s, o);
    if (lane == 0) g_loss[warp] = logf(s) - g_pos[warp];
}

// ---------------- kernel 5: mean ----------------
__global__ void reduce2_kernel(float* __restrict__ out) {
    int t = threadIdx.x;   // 256
    float acc = 0.f;
    for (int r = t; r < NROWS; r += 256) acc += g_loss[r];
    #pragma unroll
    for (int o = 16; o; o >>= 1) acc += __shfl_xor_sync(0xffffffffu, acc, o);
    __shared__ float ws[8];
    if ((t & 31) == 0) ws[t >> 5] = acc;
    __syncthreads();
    if (t == 0) {
        float s = 0.f;
        #pragma unroll
        for (int i = 0; i < 8; i++) s += ws[i];
        out[0] = s * (1.0f / (float)NROWS);
    }
}

// ---------------- launch ----------------
extern "C" void kernel_launch(void* const* d_in, const int* in_sizes, int n_in,
                              void* d_out, int out_size) {
    const float* logits = (const float*)d_in[0];
    const float* label  = (const float*)d_in[1];
    float* out = (float*)d_out;

    norm_kernel<<<NROWS, 128>>>(logits, label);
    pos_kernel<<<NROWS / 8, 256>>>();
    sim_kernel<<<NTILES, 128>>>();
    reduce1_kernel<<<NROWS / 8, 256>>>();
    reduce2_kernel<<<1, 256>>>(out);
}

// round 5
// speedup vs baseline: 2.2995x; 1.1025x over previous
#include <cuda_runtime.h>
#include <cuda_bf16.h>
#include <cstdint>
#include <cmath>

#define NROWS 8192
#define BHALF 4096
#define DDIM  512
#define INV_T 14.285714285714286f
// log2(e)/T
#define EXP_SCALE 20.60992915555662f
#define SPANS 128              // one partial per 64-col span (collision-free)
#define SROW 40                // padded smem row (bf16 units): 80B, conflict-free
#define NTILES 2080            // 64*65/2 upper-triangle tiles
#define STAGE_B (128 * SROW * 2 * 2)   // bytes per stage (sA + sB) = 20480
#define SMEM_BYTES (3 * STAGE_B)       // 61440

// ---------------- device scratch (no allocation allowed) ----------------
__device__ __nv_bfloat16 g_fb16[(size_t)NROWS * DDIM];      // 8 MB normalized bf16
__device__ float         g_partial[(size_t)NROWS * SPANS];  // 4 MB [row][span]
__device__ float         g_pos [NROWS];
__device__ float         g_loss[NROWS];

// ---------------- PTX helpers (plain sm_103-legal only) ----------------
__device__ __forceinline__ uint32_t smem_u32(const void* p) {
    uint32_t a;
    asm("{ .reg .u64 t; cvta.to.shared.u64 t, %1; cvt.u32.u64 %0, t; }" : "=r"(a) : "l"(p));
    return a;
}

__device__ __forceinline__ void cp16(uint32_t s, const void* g) {
    asm volatile("cp.async.cg.shared.global [%0], [%1], 16;" :: "r"(s), "l"(g) : "memory");
}
__device__ __forceinline__ void cp_commit() {
    asm volatile("cp.async.commit_group;" ::: "memory");
}
template<int N> __device__ __forceinline__ void cp_wait() {
    asm volatile("cp.async.wait_group %0;" :: "n"(N) : "memory");
}

__device__ __forceinline__ void ldsm_x4(uint32_t* r, uint32_t addr) {
    asm volatile("ldmatrix.sync.aligned.m8n8.x4.shared.b16 {%0,%1,%2,%3}, [%4];"
                 : "=r"(r[0]), "=r"(r[1]), "=r"(r[2]), "=r"(r[3]) : "r"(addr));
}

__device__ __forceinline__ void mma16816(float* c, const uint32_t* a, uint32_t b0, uint32_t b1) {
    asm volatile(
        "mma.sync.aligned.m16n8k16.row.col.f32.bf16.bf16.f32 "
        "{%0,%1,%2,%3}, {%4,%5,%6,%7}, {%8,%9}, {%0,%1,%2,%3};"
        : "+f"(c[0]), "+f"(c[1]), "+f"(c[2]), "+f"(c[3])
        : "r"(a[0]), "r"(a[1]), "r"(a[2]), "r"(a[3]), "r"(b0), "r"(b1));
}

__device__ __forceinline__ float ex2f(float x) {
    float y;
    asm("ex2.approx.ftz.f32 %0, %1;" : "=f"(y) : "f"(x));
    return y;
}

// ---- kernel 1: fused normalize (both halves) + fp32 positives ----------------
// Block i handles the pair (row i, row i+BHALF). Reads original inputs once,
// writes only bf16 normalized rows. pos[i] = pos[i+B] = a.b/(|a||b|)/T.
__global__ void __launch_bounds__(128) norm_pos_kernel(
        const float* __restrict__ logits, const float* __restrict__ label) {
    int i = blockIdx.x;
    int t = threadIdx.x;                  // 128 threads, 1 float4 per row each
    float4 a = ((const float4*)(logits + (size_t)i * DDIM))[t];
    float4 b = ((const float4*)(label  + (size_t)i * DDIM))[t];
    float ssa = a.x * a.x + a.y * a.y + a.z * a.z + a.w * a.w;
    float ssb = b.x * b.x + b.y * b.y + b.z * b.z + b.w * b.w;
    float ab  = a.x * b.x + a.y * b.y + a.z * b.z + a.w * b.w;
    #pragma unroll
    for (int o = 16; o; o >>= 1) {
        ssa += __shfl_xor_sync(0xffffffffu, ssa, o);
        ssb += __shfl_xor_sync(0xffffffffu, ssb, o);
        ab  += __shfl_xor_sync(0xffffffffu, ab, o);
    }
    __shared__ float ws[3][4];
    if ((t & 31) == 0) {
        ws[0][t >> 5] = ssa; ws[1][t >> 5] = ssb; ws[2][t >> 5] = ab;
    }
    __syncthreads();
    float tota = ws[0][0] + ws[0][1] + ws[0][2] + ws[0][3];
    float totb = ws[1][0] + ws[1][1] + ws[1][2] + ws[1][3];
    float totab = ws[2][0] + ws[2][1] + ws[2][2] + ws[2][3];
    float sa = 1.0f / fmaxf(sqrtf(tota), 1e-12f);
    float sb = 1.0f / fmaxf(sqrtf(totb), 1e-12f);

    __nv_bfloat162 h0, h1;
    uint2 pk;
    h0.x = __float2bfloat16(a.x * sa); h0.y = __float2bfloat16(a.y * sa);
    h1.x = __float2bfloat16(a.z * sa); h1.y = __float2bfloat16(a.w * sa);
    pk.x = *reinterpret_cast<uint32_t*>(&h0);
    pk.y = *reinterpret_cast<uint32_t*>(&h1);
    ((uint2*)(g_fb16 + (size_t)i * DDIM))[t] = pk;
    h0.x = __float2bfloat16(b.x * sb); h0.y = __float2bfloat16(b.y * sb);
    h1.x = __float2bfloat16(b.z * sb); h1.y = __float2bfloat16(b.w * sb);
    pk.x = *reinterpret_cast<uint32_t*>(&h0);
    pk.y = *reinterpret_cast<uint32_t*>(&h1);
    ((uint2*)(g_fb16 + (size_t)(i + BHALF) * DDIM))[t] = pk;

    if (t == 0) {
        float p = totab * sa * sb * INV_T;
        g_pos[i] = p;
        g_pos[i + BHALF] = p;
    }
}

// ---------------- kernel 2: symmetric 128x128 sim tiles (upper triangle) -------
// 4 warps, warp tile 64x64. K chunks of 32, TRIPLE-buffered cp.async,
// one __syncthreads per chunk. Off-diagonal tiles emit both row-sums
// (span ct*2+warp_n) and col-sums (span rt*2+warp_m, transposed tile).
__global__ void __launch_bounds__(128) sim_kernel() {
    extern __shared__ char smem[];

    int tid = threadIdx.x;
    int w = tid >> 5, lane = tid & 31;
    int g = lane >> 2, t = lane & 3;
    int warp_m = w & 1, warp_n = w >> 1;

    // decode upper-triangle tile (rt, ct), ct >= rt
    int u = blockIdx.x;
    int rt = (int)((129.0 - sqrt(129.0 * 129.0 - 8.0 * (double)u)) * 0.5);
    while (64 * (rt + 1) - ((rt + 1) * rt) / 2 <= u) rt++;
    while (64 * rt - (rt * (rt - 1)) / 2 > u) rt--;
    int ct = rt + (u - (64 * rt - (rt * (rt - 1)) / 2));
    bool diag = (rt == ct);

    const __nv_bfloat16* Ag = g_fb16 + (size_t)rt * 128 * DDIM;
    const __nv_bfloat16* Bg = g_fb16 + (size_t)ct * 128 * DDIM;

    float acc[4][8][4];
    #pragma unroll
    for (int mf = 0; mf < 4; mf++)
        #pragma unroll
        for (int nf = 0; nf < 8; nf++)
            #pragma unroll
            for (int j = 0; j < 4; j++) acc[mf][nf][j] = 0.f;

    uint32_t sbase = smem_u32(smem);

    // issue one 32-wide K chunk into stage `s` (8 cp16 per thread)
    auto issue = [&](int s, int kc) {
        uint32_t aB = sbase + (uint32_t)s * STAGE_B;
        uint32_t bB = aB + 128 * SROW * 2;
        #pragma unroll
        for (int i = 0; i < 4; i++) {
            int idx = tid + 128 * i;        // 0..511
            int row = idx >> 2, seg = idx & 3;
            size_t goff = (size_t)row * DDIM + kc * 32 + seg * 8;
            uint32_t soff = (uint32_t)(row * SROW + seg * 8) * 2;
            cp16(aB + soff, Ag + goff);
            cp16(bB + soff, Bg + goff);
        }
        cp_commit();
    };

    issue(0, 0);
    issue(1, 1);

    for (int kc = 0; kc < 16; kc++) {
        cp_wait<1>();          // stage kc landed
        __syncthreads();       // everyone done reading stage (kc-1)%3 == (kc+2)%3
        if (kc + 2 < 16) issue((kc + 2) % 3, kc + 2);
        else cp_commit();      // empty group keeps wait_group accounting exact

        uint32_t aBase = sbase + (uint32_t)(kc % 3) * STAGE_B;
        uint32_t bBase = aBase + 128 * SROW * 2;

        #pragma unroll
        for (int ks = 0; ks < 2; ks++) {
            // A frags: 4 x ldmatrix.x4 (mf = 0..3)
            uint32_t afr[4][4];
            {
                int mrow = lane & 7;
                int msel = lane >> 3;                 // 0..3
                int rofs = (msel & 1) * 8 + mrow;
                int cofs = ks * 16 + (msel >> 1) * 8;
                #pragma unroll
                for (int mf = 0; mf < 4; mf++) {
                    int row = warp_m * 64 + mf * 16 + rofs;
                    ldsm_x4(afr[mf], aBase + (uint32_t)(row * SROW + cofs) * 2);
                }
            }
            // B frags: 4 x ldmatrix.x4, each covers 2 nf
            uint32_t bfr[8][2];
            {
                int mrow = lane & 7;
                int msel = lane >> 3;
                int rofs = (msel >> 1) * 8 + mrow;    // second matrix pair = nf+1
                int cofs = ks * 16 + (msel & 1) * 8;
                #pragma unroll
                for (int np = 0; np < 4; np++) {
                    uint32_t r4[4];
                    int row = warp_n * 64 + np * 16 + rofs;
                    ldsm_x4(r4, bBase + (uint32_t)(row * SROW + cofs) * 2);
                    bfr[np * 2][0]     = r4[0];
                    bfr[np * 2][1]     = r4[1];
                    bfr[np * 2 + 1][0] = r4[2];
                    bfr[np * 2 + 1][1] = r4[3];
                }
            }
            #pragma unroll
            for (int mf = 0; mf < 4; mf++)
                #pragma unroll
                for (int nf = 0; nf < 8; nf++)
                    mma16816(acc[mf][nf], afr[mf], bfr[nf][0], bfr[nf][1]);
        }
    }

    // -------- epilogue: exp, diag mask, row sums + (off-diag) col sums --------
    int rbase = rt * 128 + warp_m * 64;
    int cbase = ct * 128 + warp_n * 64;
    float rs[4][2];
    #pragma unroll
    for (int mf = 0; mf < 4; mf++) { rs[mf][0] = 0.f; rs[mf][1] = 0.f; }

    #pragma unroll
    for (int nf = 0; nf < 8; nf++) {
        float cs0 = 0.f, cs1 = 0.f;
        int c0 = cbase + nf * 8 + 2 * t;
        #pragma unroll
        for (int mf = 0; mf < 4; mf++) {
            const float* c = acc[mf][nf];
            float e0 = ex2f(c[0] * EXP_SCALE);
            float e1 = ex2f(c[1] * EXP_SCALE);
            float e2 = ex2f(c[2] * EXP_SCALE);
            float e3 = ex2f(c[3] * EXP_SCALE);
            if (diag) {
                int r0 = rbase + mf * 16 + g;
                if (c0     == r0)     e0 = 0.f;
                if (c0 + 1 == r0)     e1 = 0.f;
                if (c0     == r0 + 8) e2 = 0.f;
                if (c0 + 1 == r0 + 8) e3 = 0.f;
            }
            rs[mf][0] += e0 + e1;
            rs[mf][1] += e2 + e3;
            cs0 += e0 + e2;
            cs1 += e1 + e3;
        }
        if (!diag) {
            // reduce over g (lanes differing in bits 2..4)
            #pragma unroll
            for (int o = 4; o <= 16; o <<= 1) {
                cs0 += __shfl_xor_sync(0xffffffffu, cs0, o);
                cs1 += __shfl_xor_sync(0xffffffffu, cs1, o);
            }
            if (g == 0) {
                int span = rt * 2 + warp_m;   // transposed contribution
                g_partial[(size_t)c0 * SPANS + span]       = cs0;
                g_partial[(size_t)(c0 + 1) * SPANS + span] = cs1;
            }
        }
    }
    #pragma unroll
    for (int mf = 0; mf < 4; mf++) {
        float s0 = rs[mf][0], s1 = rs[mf][1];
        s0 += __shfl_xor_sync(0xffffffffu, s0, 1);
        s0 += __shfl_xor_sync(0xffffffffu, s0, 2);
        s1 += __shfl_xor_sync(0xffffffffu, s1, 1);
        s1 += __shfl_xor_sync(0xffffffffu, s1, 2);
        if (t == 0) {
            int r0 = rbase + mf * 16 + g;
            int span = ct * 2 + warp_n;       // row sums
            g_partial[(size_t)r0 * SPANS + span]       = s0;
            g_partial[(size_t)(r0 + 8) * SPANS + span] = s1;
        }
    }
}

// ---------------- kernel 3: per-row lse - pos (1 warp per row, float4) --------
__global__ void reduce1_kernel() {
    int warp = blockIdx.x * 8 + (threadIdx.x >> 5);
    int lane = threadIdx.x & 31;
    float4 v = ((const float4*)(g_partial + (size_t)warp * SPANS))[lane];
    float s = (v.x + v.y) + (v.z + v.w);
    #pragma unroll
    for (int o = 16; o; o >>= 1) s += __shfl_xor_sync(0xffffffffu, s, o);
    if (lane == 0) g_loss[warp] = logf(s) - g_pos[warp];
}

// ---------------- kernel 4: mean ----------------
__global__ void reduce2_kernel(float* __restrict__ out) {
    int t = threadIdx.x;   // 256
    float acc = 0.f;
    for (int r = t; r < NROWS; r += 256) acc += g_loss[r];
    #pragma unroll
    for (int o = 16; o; o >>= 1) acc += __shfl_xor_sync(0xffffffffu, acc, o);
    __shared__ float ws[8];
    if ((t & 31) == 0) ws[t >> 5] = acc;
    __syncthreads();
    if (t == 0) {
        float s = 0.f;
        #pragma unroll
        for (int i = 0; i < 8; i++) s += ws[i];
        out[0] = s * (1.0f / (float)NROWS);
    }
}

// ---------------- launch ----------------
extern "C" void kernel_launch(void* const* d_in, const int* in_sizes, int n_in,
                              void* d_out, int out_size) {
    const float* logits = (const float*)d_in[0];
    const float* label  = (const float*)d_in[1];
    float* out = (float*)d_out;

    cudaFuncSetAttribute(sim_kernel, cudaFuncAttributeMaxDynamicSharedMemorySize,
                         SMEM_BYTES);

    norm_pos_kernel<<<BHALF, 128>>>(logits, label);
    sim_kernel<<<NTILES, 128, SMEM_BYTES>>>();
    reduce1_kernel<<<NROWS / 8, 256>>>();
    reduce2_kernel<<<1, 256>>>(out);
}